// round 8
// baseline (speedup 1.0000x reference)
#include <cuda_runtime.h>

// Demolition_Conv2d: grouped conv (16 groups of 1->32, 3x3, pad 1) + bias,
// per-(cin,cout) 5-bit quant-dequant (scale=15/9), sum over cin.
//
// R8: R7 cin-pair packing (no pair-construction ALU) + NC=4 couts/thread to
// halve L1 wavefronts per FMA. Prepass builds zero-padded packed planes
// Xp[b][cp][hp][wp] = (x[2cp],x[2cp+1]); every tap is a direct 8B element.
// Per-lane magic-RNE round, integer-valued accumulation, final lane-sum.

#define CIN   16
#define COUT  32
#define HH    112
#define WW    112
#define NB    8
#define NCP   8      // cin pairs
#define HP    114    // padded height
#define WP    114    // padded width
#define NC    4      // couts per thread

typedef unsigned long long f2;

__device__ __align__(16) f2 g_X[NB * NCP * HP * WP];   // ~6.65 MB packed planes

__device__ __forceinline__ f2 pk2(float lo, float hi) {
    f2 r; asm("mov.b64 %0, {%1, %2};" : "=l"(r) : "f"(lo), "f"(hi)); return r;
}
__device__ __forceinline__ void fma2i(f2& acc, f2 a, f2 b) {
    asm("fma.rn.f32x2 %0, %1, %2, %0;" : "+l"(acc) : "l"(a), "l"(b));
}
__device__ __forceinline__ void add2i(f2& acc, f2 b) {
    asm("add.rn.f32x2 %0, %0, %1;" : "+l"(acc) : "l"(b));
}
__device__ __forceinline__ float lanesum(f2 a) {
    float lo, hi;
    asm("mov.b64 {%0, %1}, %2;" : "=f"(lo), "=f"(hi) : "l"(a));
    return lo + hi;
}

// ---------------- prepass: padded cin-pair planes (2 pairs/thread) --------
#define PPW 57   // wp pairs per row
__global__ __launch_bounds__(256)
void prepass_kernel(const float* __restrict__ x)
{
    int gid = blockIdx.x * 256 + threadIdx.x;    // [0, NB*NCP*HP*PPW)
    if (gid >= NB * NCP * HP * PPW) return;
    int pp = gid % PPW;
    int t  = gid / PPW;
    int hp = t % HP;
    int t2 = t / HP;
    int cp = t2 % NCP;
    int b  = t2 / NCP;

    int h = hp - 1;
    bool rv = (h >= 0) && (h < HH);
    const float* p0 = x + (((b * CIN + 2 * cp)     * HH + h) * WW);
    const float* p1 = x + (((b * CIN + 2 * cp + 1) * HH + h) * WW);

    ulonglong2 outv;
    int w0 = 2 * pp - 1;     // first wp's source col
    int w1 = 2 * pp;         // second wp's source col
    bool v0 = rv && (w0 >= 0) && (w0 < WW);
    bool v1 = rv && (w1 >= 0) && (w1 < WW);
    outv.x = v0 ? pk2(p0[w0], p1[w0]) : 0ULL;
    outv.y = v1 ? pk2(p0[w1], p1[w1]) : 0ULL;

    ulonglong2* dst = reinterpret_cast<ulonglong2*>(
        g_X + ((long)((b * NCP + cp) * HP + hp)) * WP) + pp;
    *dst = outv;
}

// ---------------- main kernel ----------------
__global__ __launch_bounds__(128, 4)
void demolition_conv2d_kernel(const float* __restrict__ Wt,
                              const float* __restrict__ bias,
                              float* __restrict__ out)
{
    // This block's 4 couts: [cp][lc][w0..w8, bias], lanes = (cin 2cp, 2cp+1),
    // pre-scaled by SCALE.
    __shared__ __align__(16) f2 sW[NCP * NC * 10];   // 2560 B

    const float SCALEf = 15.0f / 9.0f;
    const float INVf   = 9.0f / 15.0f;
    const float MAGICf = 12582912.0f;   // 1.5 * 2^23

    // g in [0, 200704). 25088 4-px tiles; cout group (8) uniform per block
    // (25088 = 196 * 128).
    int g = blockIdx.x * 128 + threadIdx.x;
    int grp = g / 25088;                 // 0..7
    int t  = g % 25088;
    int wt = t % 28;                     // 4-px tile in row
    int t1 = t / 28;
    int h  = t1 % HH;
    int b  = t1 / HH;
    int w0 = wt * 4;
    int co_base = grp * NC;

    for (int i = threadIdx.x; i < NCP * NC * 10; i += 128) {
        int e  = i / 10;
        int k  = i % 10;
        int cp = e / NC;
        int lc = e % NC;
        int co = co_base + lc;
        float v0, v1;
        if (k < 9) {
            v0 = Wt[((2 * cp)     * COUT + co) * 9 + k];
            v1 = Wt[((2 * cp + 1) * COUT + co) * 9 + k];
        } else {
            v0 = bias[(2 * cp)     * COUT + co];
            v1 = bias[(2 * cp + 1) * COUT + co];
        }
        sW[i] = pk2(v0 * SCALEf, v1 * SCALEf);
    }
    __syncthreads();

    const f2 MAG2  = pk2(MAGICf,  MAGICf);
    const f2 NMAG2 = pk2(-MAGICf, -MAGICf);

    f2 acc[NC][4];
#pragma unroll
    for (int c = 0; c < NC; ++c)
#pragma unroll
        for (int j = 0; j < 4; ++j) acc[c][j] = 0ULL;

#pragma unroll 1
    for (int cp = 0; cp < NCP; ++cp) {
        // Taps: 3 padded rows (hp = h..h+2), 6 f2 each (wp = w0..w0+5).
        const f2* base = g_X + ((long)(b * NCP + cp) * HP + h) * WP + w0;

        f2 tp[3][6];
#pragma unroll
        for (int r = 0; r < 3; ++r) {
            const ulonglong2* rp = reinterpret_cast<const ulonglong2*>(base + r * WP);
            ulonglong2 A = rp[0];
            ulonglong2 B = rp[1];
            ulonglong2 C = rp[2];
            tp[r][0] = A.x; tp[r][1] = A.y;
            tp[r][2] = B.x; tp[r][3] = B.y;
            tp[r][4] = C.x; tp[r][5] = C.y;
        }

        const ulonglong2* wb =
            reinterpret_cast<const ulonglong2*>(&sW[cp * NC * 10]);

#pragma unroll
        for (int c = 0; c < NC; ++c) {
            ulonglong2 w01 = wb[c * 5 + 0];   // w0, w1
            ulonglong2 w23 = wb[c * 5 + 1];   // w2, w3
            ulonglong2 w45 = wb[c * 5 + 2];   // w4, w5
            ulonglong2 w67 = wb[c * 5 + 3];   // w6, w7
            ulonglong2 w8b = wb[c * 5 + 4];   // w8, bias

#pragma unroll
            for (int j = 0; j < 4; ++j) {
                f2 y = w8b.y;
                fma2i(y, tp[0][j],     w01.x);
                fma2i(y, tp[0][j + 1], w01.y);
                fma2i(y, tp[0][j + 2], w23.x);
                fma2i(y, tp[1][j],     w23.y);
                fma2i(y, tp[1][j + 1], w45.x);
                fma2i(y, tp[1][j + 2], w45.y);
                fma2i(y, tp[2][j],     w67.x);
                fma2i(y, tp[2][j + 1], w67.y);
                fma2i(y, tp[2][j + 2], w8b.x);

                add2i(y, MAG2);          // per-lane RNE -> integer
                add2i(y, NMAG2);
                add2i(acc[c][j], y);     // exact integer-valued sums
            }
        }
    }

    // Final: sum the two cin lanes, scale by 1/SCALE, store 4 px per cout.
#pragma unroll
    for (int c = 0; c < NC; ++c) {
        int co = co_base + c;
        float4 v;
        v.x = lanesum(acc[c][0]) * INVf;
        v.y = lanesum(acc[c][1]) * INVf;
        v.z = lanesum(acc[c][2]) * INVf;
        v.w = lanesum(acc[c][3]) * INVf;
        float* ob = out + ((long)(b * COUT + co) * HH + h) * WW + w0;
        *reinterpret_cast<float4*>(ob) = v;
    }
}

extern "C" void kernel_launch(void* const* d_in, const int* in_sizes, int n_in,
                              void* d_out, int out_size)
{
    const float* x    = (const float*)d_in[0];   // [8,16,112,112]
    const float* Wt   = (const float*)d_in[1];   // [16,32,1,3,3]
    const float* bias = (const float*)d_in[2];   // [16,32]
    float* out        = (float*)d_out;           // [8,32,112,112]

    // NB*NCP*HP*PPW = 415872 -> 1625 blocks of 256 (guarded).
    prepass_kernel<<<1625, 256>>>(x);
    // 200704 threads = 1568 blocks * 128.
    demolition_conv2d_kernel<<<1568, 128>>>(Wt, bias, out);
}

// round 9
// speedup vs baseline: 1.2637x; 1.2637x over previous
#include <cuda_runtime.h>

// Demolition_Conv2d: grouped conv (16 groups of 1->32, 3x3, pad 1) + bias,
// per-(cin,cout) 5-bit quant-dequant (scale=15/9), sum over cin.
//
// R9: cin-pair packed planes (R7) + LANE-CONTIGUOUS tap loads. A warp covers
// 64 consecutive pixels as 2 slots (lane, lane+32); each tap is a warp-
// coalesced LDG.64 (2 wavefronts vs ~16 for the old strided LDG.128s).
// Weights broadcast from smem (dedup). Per-lane magic-RNE, integer acc.

#define CIN   16
#define COUT  32
#define HH    112
#define WW    112
#define NB    8
#define NCP   8      // cin pairs
#define HP    114    // padded height
#define WP    114    // padded width
#define NC    4      // couts per thread
#define NPIX  (NB * HH * WW)   // 100352

typedef unsigned long long f2;

__device__ __align__(16) f2 g_X[NB * NCP * HP * WP];   // ~6.65 MB packed planes

__device__ __forceinline__ f2 pk2(float lo, float hi) {
    f2 r; asm("mov.b64 %0, {%1, %2};" : "=l"(r) : "f"(lo), "f"(hi)); return r;
}
__device__ __forceinline__ void fma2i(f2& acc, f2 a, f2 b) {
    asm("fma.rn.f32x2 %0, %1, %2, %0;" : "+l"(acc) : "l"(a), "l"(b));
}
__device__ __forceinline__ void add2i(f2& acc, f2 b) {
    asm("add.rn.f32x2 %0, %0, %1;" : "+l"(acc) : "l"(b));
}
__device__ __forceinline__ float lanesum(f2 a) {
    float lo, hi;
    asm("mov.b64 {%0, %1}, %2;" : "=f"(lo), "=f"(hi) : "l"(a));
    return lo + hi;
}

// ---------------- prepass: padded cin-pair planes (2 pairs/thread) --------
#define PPW 57   // wp pairs per row
__global__ __launch_bounds__(256)
void prepass_kernel(const float* __restrict__ x)
{
    int gid = blockIdx.x * 256 + threadIdx.x;    // [0, NB*NCP*HP*PPW)
    if (gid >= NB * NCP * HP * PPW) return;
    int pp = gid % PPW;
    int t  = gid / PPW;
    int hp = t % HP;
    int t2 = t / HP;
    int cp = t2 % NCP;
    int b  = t2 / NCP;

    int h = hp - 1;
    bool rv = (h >= 0) && (h < HH);
    const float* p0 = x + (((b * CIN + 2 * cp)     * HH + h) * WW);
    const float* p1 = x + (((b * CIN + 2 * cp + 1) * HH + h) * WW);

    ulonglong2 outv;
    int w0 = 2 * pp - 1;
    int w1 = 2 * pp;
    bool v0 = rv && (w0 >= 0) && (w0 < WW);
    bool v1 = rv && (w1 >= 0) && (w1 < WW);
    outv.x = v0 ? pk2(p0[w0], p1[w0]) : 0ULL;
    outv.y = v1 ? pk2(p0[w1], p1[w1]) : 0ULL;

    ulonglong2* dst = reinterpret_cast<ulonglong2*>(
        g_X + ((long)((b * NCP + cp) * HP + hp)) * WP) + pp;
    *dst = outv;
}

// ---------------- main kernel ----------------
// 12544 warps: grp = warp/1568 (uniform per block: 392 blocks per group),
// warp-chunk wc = warp%1568 covers pixels [wc*64, wc*64+64).
__global__ __launch_bounds__(128, 4)
void demolition_conv2d_kernel(const float* __restrict__ Wt,
                              const float* __restrict__ bias,
                              float* __restrict__ out)
{
    __shared__ __align__(16) f2 sW[NCP * NC * 10];   // 2560 B

    const float SCALEf = 15.0f / 9.0f;
    const float INVf   = 9.0f / 15.0f;
    const float MAGICf = 12582912.0f;   // 1.5 * 2^23

    int tid  = threadIdx.x;
    int warp = blockIdx.x * 4 + (tid >> 5);
    int lane = tid & 31;
    int grp  = warp / 1568;              // 0..7, uniform per block
    int wc   = warp % 1568;
    int co_base = grp * NC;

    // Two pixels per thread, lane-contiguous within the warp.
    int p0 = wc * 64 + lane;
    int p1 = p0 + 32;

    int b0 = p0 / (HH * WW);
    int r0 = p0 % (HH * WW);
    int h0 = r0 / WW;
    int w0 = r0 % WW;
    int b1 = p1 / (HH * WW);
    int r1 = p1 % (HH * WW);
    int h1 = r1 / WW;
    int w1 = r1 % WW;

    // Stage this group's weights: [cp][lc][w0..w8,bias], lanes=(2cp,2cp+1)*S.
    for (int i = tid; i < NCP * NC * 10; i += 128) {
        int e  = i / 10;
        int k  = i % 10;
        int cp = e / NC;
        int lc = e % NC;
        int co = co_base + lc;
        float v0, v1;
        if (k < 9) {
            v0 = Wt[((2 * cp)     * COUT + co) * 9 + k];
            v1 = Wt[((2 * cp + 1) * COUT + co) * 9 + k];
        } else {
            v0 = bias[(2 * cp)     * COUT + co];
            v1 = bias[(2 * cp + 1) * COUT + co];
        }
        sW[i] = pk2(v0 * SCALEf, v1 * SCALEf);
    }
    __syncthreads();

    const f2 MAG2  = pk2(MAGICf,  MAGICf);
    const f2 NMAG2 = pk2(-MAGICf, -MAGICf);

    f2 acc[NC][2];
#pragma unroll
    for (int c = 0; c < NC; ++c) { acc[c][0] = 0ULL; acc[c][1] = 0ULL; }

    // Plane base pointers (advance by HP*WP per cp).
    const f2* A = g_X + ((long)b0 * NCP * HP + h0) * WP + w0;
    const f2* Bq = g_X + ((long)b1 * NCP * HP + h1) * WP + w1;

#pragma unroll 1
    for (int cp = 0; cp < NCP; ++cp) {
        // 9 taps per slot, scalar 8B loads, warp-coalesced.
        f2 ta[9], tb[9];
#pragma unroll
        for (int r = 0; r < 3; ++r) {
#pragma unroll
            for (int k = 0; k < 3; ++k) {
                ta[r * 3 + k] = A[r * WP + k];
                tb[r * 3 + k] = Bq[r * WP + k];
            }
        }
        A  += (long)HP * WP;
        Bq += (long)HP * WP;

        const ulonglong2* wb =
            reinterpret_cast<const ulonglong2*>(&sW[cp * NC * 10]);

#pragma unroll
        for (int c = 0; c < NC; ++c) {
            ulonglong2 w01 = wb[c * 5 + 0];
            ulonglong2 w23 = wb[c * 5 + 1];
            ulonglong2 w45 = wb[c * 5 + 2];
            ulonglong2 w67 = wb[c * 5 + 3];
            ulonglong2 w8b = wb[c * 5 + 4];   // w8, bias

            f2 y0 = w8b.y;
            f2 y1 = w8b.y;
            fma2i(y0, ta[0], w01.x);  fma2i(y1, tb[0], w01.x);
            fma2i(y0, ta[1], w01.y);  fma2i(y1, tb[1], w01.y);
            fma2i(y0, ta[2], w23.x);  fma2i(y1, tb[2], w23.x);
            fma2i(y0, ta[3], w23.y);  fma2i(y1, tb[3], w23.y);
            fma2i(y0, ta[4], w45.x);  fma2i(y1, tb[4], w45.x);
            fma2i(y0, ta[5], w45.y);  fma2i(y1, tb[5], w45.y);
            fma2i(y0, ta[6], w67.x);  fma2i(y1, tb[6], w67.x);
            fma2i(y0, ta[7], w67.y);  fma2i(y1, tb[7], w67.y);
            fma2i(y0, ta[8], w8b.x);  fma2i(y1, tb[8], w8b.x);

            add2i(y0, MAG2);  add2i(y0, NMAG2);   // per-lane RNE -> integer
            add2i(y1, MAG2);  add2i(y1, NMAG2);
            add2i(acc[c][0], y0);
            add2i(acc[c][1], y1);
        }
    }

    // Stores: scalar, warp-coalesced (lanes contiguous in w).
#pragma unroll
    for (int c = 0; c < NC; ++c) {
        int co = co_base + c;
        out[((long)(b0 * COUT + co) * HH + h0) * WW + w0] = lanesum(acc[c][0]) * INVf;
        out[((long)(b1 * COUT + co) * HH + h1) * WW + w1] = lanesum(acc[c][1]) * INVf;
    }
}

extern "C" void kernel_launch(void* const* d_in, const int* in_sizes, int n_in,
                              void* d_out, int out_size)
{
    const float* x    = (const float*)d_in[0];   // [8,16,112,112]
    const float* Wt   = (const float*)d_in[1];   // [16,32,1,3,3]
    const float* bias = (const float*)d_in[2];   // [16,32]
    float* out        = (float*)d_out;           // [8,32,112,112]

    // NB*NCP*HP*PPW = 415872 -> 1625 blocks of 256 (guarded).
    prepass_kernel<<<1625, 256>>>(x);
    // 12544 warps = 3136 blocks * 4 warps.
    demolition_conv2d_kernel<<<3136, 128>>>(Wt, bias, out);
}

// round 10
// speedup vs baseline: 1.6221x; 1.2837x over previous
#include <cuda_runtime.h>

// Demolition_Conv2d: grouped conv (16 groups of 1->32, 3x3, pad 1) + bias,
// per-(cin,cout) 5-bit quant-dequant (scale=15/9), sum over cin.
//
// R10: cin-pair packed planes + VERTICAL 4-pixel slots. Each thread: 4
// vertically adjacent pixels (rows h0..h0+3, same w) x 4 couts. Taps = 6
// rows x 3 cols LDG.64 (coalesced in w) feed 4 pixels -> tap traffic halves;
// each weight LDS.128 feeds 144 FMA2 -> weight cost per FMA halves. Kernel
// becomes FMA-pipe bound. Per-lane magic-RNE, integer acc, final lane-sum.

#define CIN   16
#define COUT  32
#define HH    112
#define WW    112
#define NB    8
#define NCP   8      // cin pairs
#define HP    114    // padded height
#define WP    114    // padded width
#define NC    4      // couts per thread
#define NS    4      // vertical pixel slots per thread

typedef unsigned long long f2;

__device__ __align__(16) f2 g_X[NB * NCP * HP * WP];   // ~6.65 MB packed planes

__device__ __forceinline__ f2 pk2(float lo, float hi) {
    f2 r; asm("mov.b64 %0, {%1, %2};" : "=l"(r) : "f"(lo), "f"(hi)); return r;
}
__device__ __forceinline__ void fma2i(f2& acc, f2 a, f2 b) {
    asm("fma.rn.f32x2 %0, %1, %2, %0;" : "+l"(acc) : "l"(a), "l"(b));
}
__device__ __forceinline__ void add2i(f2& acc, f2 b) {
    asm("add.rn.f32x2 %0, %0, %1;" : "+l"(acc) : "l"(b));
}
__device__ __forceinline__ float lanesum(f2 a) {
    float lo, hi;
    asm("mov.b64 {%0, %1}, %2;" : "=f"(lo), "=f"(hi) : "l"(a));
    return lo + hi;
}

// ---------------- prepass: padded cin-pair planes (2 pairs/thread) --------
#define PPW 57   // wp pairs per row
__global__ __launch_bounds__(256)
void prepass_kernel(const float* __restrict__ x)
{
    int gid = blockIdx.x * 256 + threadIdx.x;    // [0, NB*NCP*HP*PPW)
    if (gid >= NB * NCP * HP * PPW) return;
    int pp = gid % PPW;
    int t  = gid / PPW;
    int hp = t % HP;
    int t2 = t / HP;
    int cp = t2 % NCP;
    int b  = t2 / NCP;

    int h = hp - 1;
    bool rv = (h >= 0) && (h < HH);
    const float* p0 = x + (((b * CIN + 2 * cp)     * HH + h) * WW);
    const float* p1 = x + (((b * CIN + 2 * cp + 1) * HH + h) * WW);

    ulonglong2 outv;
    int w0 = 2 * pp - 1;
    int w1 = 2 * pp;
    bool v0 = rv && (w0 >= 0) && (w0 < WW);
    bool v1 = rv && (w1 >= 0) && (w1 < WW);
    outv.x = v0 ? pk2(p0[w0], p1[w0]) : 0ULL;
    outv.y = v1 ? pk2(p0[w1], p1[w1]) : 0ULL;

    ulonglong2* dst = reinterpret_cast<ulonglong2*>(
        g_X + ((long)((b * NCP + cp) * HP + hp)) * WP) + pp;
    *dst = outv;
}

// ---------------- main kernel ----------------
// 200704 threads = 1568 blocks x 128. grp = g/25088 uniform per block
// (25088 = 196*128). q = g%25088 -> (b, band, w): w = q%112,
// band = (q/112)%28, b = q/3136, h0 = band*4.
__global__ __launch_bounds__(128, 4)
void demolition_conv2d_kernel(const float* __restrict__ Wt,
                              const float* __restrict__ bias,
                              float* __restrict__ out)
{
    __shared__ __align__(16) f2 sW[NCP * NC * 10];   // 2560 B

    const float SCALEf = 15.0f / 9.0f;
    const float INVf   = 9.0f / 15.0f;
    const float MAGICf = 12582912.0f;   // 1.5 * 2^23

    int g = blockIdx.x * 128 + threadIdx.x;
    int grp = g / 25088;                 // 0..7
    int q   = g % 25088;
    int w    = q % WW;
    int band = (q / WW) % 28;
    int b    = q / (WW * 28);
    int h0   = band * NS;
    int co_base = grp * NC;

    for (int i = threadIdx.x; i < NCP * NC * 10; i += 128) {
        int e  = i / 10;
        int k  = i % 10;
        int cp = e / NC;
        int lc = e % NC;
        int co = co_base + lc;
        float v0, v1;
        if (k < 9) {
            v0 = Wt[((2 * cp)     * COUT + co) * 9 + k];
            v1 = Wt[((2 * cp + 1) * COUT + co) * 9 + k];
        } else {
            v0 = bias[(2 * cp)     * COUT + co];
            v1 = bias[(2 * cp + 1) * COUT + co];
        }
        sW[i] = pk2(v0 * SCALEf, v1 * SCALEf);
    }
    __syncthreads();

    const f2 MAG2  = pk2(MAGICf,  MAGICf);
    const f2 NMAG2 = pk2(-MAGICf, -MAGICf);

    f2 acc[NC][NS];
#pragma unroll
    for (int c = 0; c < NC; ++c)
#pragma unroll
        for (int s = 0; s < NS; ++s) acc[c][s] = 0ULL;

    // Padded plane pointer for cp=0: rows h0..h0+5 cover outputs h0..h0+3.
    const f2* A = g_X + ((long)b * NCP * HP + h0) * WP + w;

#pragma unroll 1
    for (int cp = 0; cp < NCP; ++cp) {
        // 6 rows x 3 cols of taps (coalesced LDG.64 in w).
        f2 tp[6][3];
#pragma unroll
        for (int r = 0; r < 6; ++r) {
#pragma unroll
            for (int k = 0; k < 3; ++k)
                tp[r][k] = A[r * WP + k];
        }
        A += (long)HP * WP;

        const ulonglong2* wb =
            reinterpret_cast<const ulonglong2*>(&sW[cp * NC * 10]);

#pragma unroll
        for (int c = 0; c < NC; ++c) {
            ulonglong2 w01 = wb[c * 5 + 0];   // w0, w1
            ulonglong2 w23 = wb[c * 5 + 1];   // w2, w3
            ulonglong2 w45 = wb[c * 5 + 2];   // w4, w5
            ulonglong2 w67 = wb[c * 5 + 3];   // w6, w7
            ulonglong2 w8b = wb[c * 5 + 4];   // w8, bias

#pragma unroll
            for (int s = 0; s < NS; ++s) {
                f2 y = w8b.y;
                fma2i(y, tp[s][0],     w01.x);
                fma2i(y, tp[s][1],     w01.y);
                fma2i(y, tp[s][2],     w23.x);
                fma2i(y, tp[s + 1][0], w23.y);
                fma2i(y, tp[s + 1][1], w45.x);
                fma2i(y, tp[s + 1][2], w45.y);
                fma2i(y, tp[s + 2][0], w67.x);
                fma2i(y, tp[s + 2][1], w67.y);
                fma2i(y, tp[s + 2][2], w8b.x);

                add2i(y, MAG2);           // per-lane RNE -> integer
                add2i(y, NMAG2);
                add2i(acc[c][s], y);      // exact integer-valued sums
            }
        }
    }

    // Stores: scalar, coalesced in w. 16 stores (4 couts x 4 rows).
#pragma unroll
    for (int c = 0; c < NC; ++c) {
        int co = co_base + c;
        float* ob = out + ((long)(b * COUT + co) * HH + h0) * WW + w;
#pragma unroll
        for (int s = 0; s < NS; ++s)
            ob[s * WW] = lanesum(acc[c][s]) * INVf;
    }
}

extern "C" void kernel_launch(void* const* d_in, const int* in_sizes, int n_in,
                              void* d_out, int out_size)
{
    const float* x    = (const float*)d_in[0];   // [8,16,112,112]
    const float* Wt   = (const float*)d_in[1];   // [16,32,1,3,3]
    const float* bias = (const float*)d_in[2];   // [16,32]
    float* out        = (float*)d_out;           // [8,32,112,112]

    // NB*NCP*HP*PPW = 415872 -> 1625 blocks of 256 (guarded).
    prepass_kernel<<<1625, 256>>>(x);
    // 200704 threads = 1568 blocks * 128.
    demolition_conv2d_kernel<<<1568, 128>>>(Wt, bias, out);
}